// round 10
// baseline (speedup 1.0000x reference)
#include <cuda_runtime.h>

// TransformDomainInterpolator, GB300 (sm_103a).
//
// Math: fc = M/2 keeps ALL 2048 DFT bins -> exact 2x bandlimited interp:
//   out[2m]   = x[m]
//   out[2m+1] = IDFT2048( DFT2048(x)[k] * w[k] )/2048,
//     w[k] = e^{+i*pi*k/2048} (k<1024), -e^{+i*pi*k/2048} (k>=1024)
// Time: out[t] = lerp(H2, H11, clamp((t-2)/9, 0, 1)).
//
// Radix-8 register FFT: 512 threads, halves own one pilot row each with
// 8 elems/thread. Phases: fwd{10,9,8}(regs) | fwd{7,6,5} | fwd{4,3} |
// MID fwd{2,1,0}+pointwise+inv{0,1,2} (contiguous octet, all regs) |
// inv{3,4} | inv{5,6,7} | inv{8,9,10}. 8 barriers.
// RACE FIX vs R9: every phase reads AND writes the same padded PIDX slots
// (per-thread in-place, disjoint across threads). iP1 no longer writes
// unpadded natural positions; the epilogue reads PIDX(m) instead.

#define THREADS 512
#define MM 2048
#define NSYM 14
#define PADN 2176
#define PIDX(i) ((i) + ((i) >> 4))
#define C8v  0.70710678118654752f
#define CP8v 0.92387953251128676f
#define SP8v 0.38268343236508977f

static __device__ __forceinline__ float2 cmul(float2 a, float2 b) {
    return make_float2(fmaf(a.x, b.x, -a.y * b.y), fmaf(a.x, b.y, a.y * b.x));
}
static __device__ __forceinline__ float2 cadd(float2 a, float2 b) {
    return make_float2(a.x + b.x, a.y + b.y);
}
static __device__ __forceinline__ float2 csub(float2 a, float2 b) {
    return make_float2(a.x - b.x, a.y - b.y);
}

// ---- radix-4 fused DIF stages (S+1, S); group id g
template <int S>
static __device__ __forceinline__ void fwd4(float2* __restrict__ y,
                                            const float2* __restrict__ tw, int g)
{
    const int h1 = 1 << S;
    const int j  = g & (h1 - 1);
    const int i0 = ((g >> S) << (S + 2)) | j;
    float2 w  = tw[j << (9 - S)];
    float2 wm = make_float2(w.y, -w.x);
    float2 v  = tw[j << (10 - S)];
    float2 a = y[PIDX(i0)], bb = y[PIDX(i0 + h1)];
    float2 c = y[PIDX(i0 + 2 * h1)], d = y[PIDX(i0 + 3 * h1)];
    float2 a1 = cadd(a, c),  c1 = cmul(csub(a, c), w);
    float2 b1 = cadd(bb, d), d1 = cmul(csub(bb, d), wm);
    y[PIDX(i0)]          = cadd(a1, b1);
    y[PIDX(i0 + h1)]     = cmul(csub(a1, b1), v);
    y[PIDX(i0 + 2 * h1)] = cadd(c1, d1);
    y[PIDX(i0 + 3 * h1)] = cmul(csub(c1, d1), v);
}

// ---- radix-4 fused DIT stages (S, S+1), conjugate twiddles
template <int S>
static __device__ __forceinline__ void inv4(float2* __restrict__ y,
                                            const float2* __restrict__ tw, int g)
{
    const int h1 = 1 << S;
    const int j  = g & (h1 - 1);
    const int i0 = ((g >> S) << (S + 2)) | j;
    float2 w   = tw[j << (9 - S)];
    float2 cw  = make_float2(w.x, -w.y);
    float2 cw2 = make_float2(w.y, w.x);
    float2 v0  = tw[j << (10 - S)];
    float2 cv  = make_float2(v0.x, -v0.y);
    float2 a = y[PIDX(i0)], bb = y[PIDX(i0 + h1)];
    float2 c = y[PIDX(i0 + 2 * h1)], d = y[PIDX(i0 + 3 * h1)];
    float2 t  = cmul(bb, cv);
    float2 a1 = cadd(a, t), b1 = csub(a, t);
    t = cmul(d, cv);
    float2 c1 = cadd(c, t), d1 = csub(c, t);
    t = cmul(c1, cw);
    y[PIDX(i0)]          = cadd(a1, t);
    y[PIDX(i0 + 2 * h1)] = csub(a1, t);
    t = cmul(d1, cw2);
    y[PIDX(i0 + h1)]     = cadd(b1, t);
    y[PIDX(i0 + 3 * h1)] = csub(b1, t);
}

// ---- radix-8 fused DIF stages (S+2, S+1, S); smem read/write, 256-thread q
template <int S>
static __device__ __forceinline__ void fwd8(float2* __restrict__ y,
                                            const float2* __restrict__ tw, int q)
{
    const int h  = 1 << S;
    const int j  = q & (h - 1);
    const int i0 = ((q >> S) << (S + 3)) | j;
    float2 x[8];
    #pragma unroll
    for (int r = 0; r < 8; ++r) x[r] = y[PIDX(i0 + r * h)];
    #pragma unroll
    for (int r = 0; r < 4; ++r) {
        float2 wa = tw[(j + r * h) << (8 - S)];
        float2 u = x[r], v = x[r + 4];
        x[r] = cadd(u, v);
        x[r + 4] = cmul(csub(u, v), wa);
    }
    float2 wb0 = tw[j << (9 - S)];
    float2 wb1 = make_float2(wb0.y, -wb0.x);
    #pragma unroll
    for (int o = 0; o < 8; o += 4) {
        float2 u = x[o], v = x[o + 2];
        x[o] = cadd(u, v); x[o + 2] = cmul(csub(u, v), wb0);
        u = x[o + 1]; v = x[o + 3];
        x[o + 1] = cadd(u, v); x[o + 3] = cmul(csub(u, v), wb1);
    }
    float2 wc = tw[j << (10 - S)];
    #pragma unroll
    for (int g = 0; g < 4; ++g) {
        float2 u = x[2 * g], v = x[2 * g + 1];
        x[2 * g] = cadd(u, v); x[2 * g + 1] = cmul(csub(u, v), wc);
    }
    #pragma unroll
    for (int r = 0; r < 8; ++r) y[PIDX(i0 + r * h)] = x[r];
}

// ---- radix-8 fused DIT stages (S, S+1, S+2), conjugate twiddles
template <int S>
static __device__ __forceinline__ void inv8(float2* __restrict__ y,
                                            const float2* __restrict__ tw, int q)
{
    const int h  = 1 << S;
    const int j  = q & (h - 1);
    const int i0 = ((q >> S) << (S + 3)) | j;
    float2 x[8];
    #pragma unroll
    for (int r = 0; r < 8; ++r) x[r] = y[PIDX(i0 + r * h)];
    float2 wc0 = tw[j << (10 - S)];
    float2 wc  = make_float2(wc0.x, -wc0.y);
    #pragma unroll
    for (int g = 0; g < 4; ++g) {
        float2 v = cmul(x[2 * g + 1], wc);
        float2 u = x[2 * g];
        x[2 * g] = cadd(u, v); x[2 * g + 1] = csub(u, v);
    }
    float2 wb0  = tw[j << (9 - S)];
    float2 wb0c = make_float2(wb0.x, -wb0.y);
    float2 wb1c = make_float2(wb0.y, wb0.x);
    #pragma unroll
    for (int o = 0; o < 8; o += 4) {
        float2 v = cmul(x[o + 2], wb0c);
        float2 u = x[o];
        x[o] = cadd(u, v); x[o + 2] = csub(u, v);
        v = cmul(x[o + 3], wb1c);
        u = x[o + 1];
        x[o + 1] = cadd(u, v); x[o + 3] = csub(u, v);
    }
    #pragma unroll
    for (int r = 0; r < 4; ++r) {
        float2 wa0 = tw[(j + r * h) << (8 - S)];
        float2 wac = make_float2(wa0.x, -wa0.y);
        float2 v = cmul(x[r + 4], wac);
        float2 u = x[r];
        x[r] = cadd(u, v); x[r + 4] = csub(u, v);
    }
    #pragma unroll
    for (int r = 0; r < 8; ++r) y[PIDX(i0 + r * h)] = x[r];
}

// MODE 0: real-only f32 output. MODE 1: interleaved complex-as-f32 output.
template <int MODE>
__global__ void __launch_bounds__(THREADS, 3) tdi_kernel(
    const float* __restrict__ re,
    const float* __restrict__ im,
    void* __restrict__ outv)
{
    __shared__ float2 tw[1024];      // e^{-i*pi*t/1024}
    __shared__ float2 y2s[PADN];
    __shared__ float2 y11s[PADN];

    const int b   = blockIdx.x;
    const int tid = threadIdx.x;
    const int row = tid >> 8;        // 0 -> sym2, 1 -> sym11
    const int q   = tid & 255;
    float2* __restrict__ y = row ? y11s : y2s;

    for (int t = tid; t < 1024; t += THREADS) {
        float s, c;
        sincospif(-(float)t * (1.0f / 1024.0f), &s, &c);
        tw[t] = make_float2(c, s);
    }

    const float* rb  = re + (size_t)b * 4096;
    const float* ib  = im + (size_t)b * 4096;
    const float* rbr = rb + row * MM;
    const float* ibr = ib + row * MM;

    float2 x[8];
    #pragma unroll
    for (int r = 0; r < 8; ++r)
        x[r] = make_float2(rbr[q + 256 * r], ibr[q + 256 * r]);
    __syncthreads();                                  // tw ready

    // ---- P1: fwd stages 10,9,8 (h=256, j=q) from registers
    #pragma unroll
    for (int r = 0; r < 4; ++r) {
        float2 wa = tw[q + 256 * r];
        float2 u = x[r], v = x[r + 4];
        x[r] = cadd(u, v);
        x[r + 4] = cmul(csub(u, v), wa);
    }
    {
        float2 wb0 = tw[q << 1];
        float2 wb1 = make_float2(wb0.y, -wb0.x);
        #pragma unroll
        for (int o = 0; o < 8; o += 4) {
            float2 u = x[o], v = x[o + 2];
            x[o] = cadd(u, v); x[o + 2] = cmul(csub(u, v), wb0);
            u = x[o + 1]; v = x[o + 3];
            x[o + 1] = cadd(u, v); x[o + 3] = cmul(csub(u, v), wb1);
        }
        float2 wc = tw[q << 2];
        #pragma unroll
        for (int g = 0; g < 4; ++g) {
            float2 u = x[2 * g], v = x[2 * g + 1];
            x[2 * g] = cadd(u, v); x[2 * g + 1] = cmul(csub(u, v), wc);
        }
    }
    #pragma unroll
    for (int r = 0; r < 8; ++r) y[PIDX(q + 256 * r)] = x[r];
    __syncthreads();

    fwd8<5>(y, tw, q);                                // stages 7,6,5
    __syncthreads();
    fwd4<3>(y, tw, 2 * q); fwd4<3>(y, tw, 2 * q + 1); // stages 4,3
    __syncthreads();

    // ---- MID: fwd 2,1,0 + pointwise + inv 0,1,2 on 8 contiguous elems
    {
        const int p = 8 * q;
        #pragma unroll
        for (int r = 0; r < 8; ++r) x[r] = y[PIDX(p + r)];
        // fwd H=4: W = e^{-i*pi*r/4}
        { float2 u=x[0], v=x[4]; x[0]=cadd(u,v); x[4]=csub(u,v); }
        { float2 u=x[1], v=x[5]; x[1]=cadd(u,v);
          x[5]=cmul(csub(u,v), make_float2(C8v,-C8v)); }
        { float2 u=x[2], v=x[6]; x[2]=cadd(u,v);
          float2 t=csub(u,v); x[6]=make_float2(t.y,-t.x); }
        { float2 u=x[3], v=x[7]; x[3]=cadd(u,v);
          x[7]=cmul(csub(u,v), make_float2(-C8v,-C8v)); }
        // fwd H=2: W(0)=1, W(1)=-i
        #pragma unroll
        for (int o = 0; o < 8; o += 4) {
            float2 u=x[o], v=x[o+2]; x[o]=cadd(u,v); x[o+2]=csub(u,v);
            u=x[o+1]; v=x[o+3]; x[o+1]=cadd(u,v);
            float2 t=csub(u,v); x[o+3]=make_float2(t.y,-t.x);
        }
        // fwd H=1
        #pragma unroll
        for (int g = 0; g < 4; ++g) {
            float2 u=x[2*g], v=x[2*g+1];
            x[2*g]=cadd(u,v); x[2*g+1]=csub(u,v);
        }
        // pointwise: k = brev8(q) + 256*brev3(r); sign=(-1)^(r&1); scale 1/2048
        {
            const float K = 1.0f / 2048.0f;
            int kq = (int)(__brev((unsigned)q) >> 24);
            float sv, cv;
            sincospif((float)kq * (1.0f / 2048.0f), &sv, &cv);
            float2 base = make_float2(cv, sv);        // e^{+i*pi*kq/2048}
            const float2 S8[8] = {
                { K, 0.0f }, { 0.0f, -K },
                { K*C8v,  K*C8v }, { K*C8v, -K*C8v },
                { K*CP8v, K*SP8v }, { K*SP8v, -K*CP8v },
                { K*SP8v, K*CP8v }, { K*CP8v, -K*SP8v } };
            #pragma unroll
            for (int r = 0; r < 8; ++r) x[r] = cmul(x[r], cmul(base, S8[r]));
        }
        // inv H=1
        #pragma unroll
        for (int g = 0; g < 4; ++g) {
            float2 u=x[2*g], v=x[2*g+1];
            x[2*g]=cadd(u,v); x[2*g+1]=csub(u,v);
        }
        // inv H=2: conjW(0)=1, conjW(1)=+i
        #pragma unroll
        for (int o = 0; o < 8; o += 4) {
            float2 u=x[o], v=x[o+2]; x[o]=cadd(u,v); x[o+2]=csub(u,v);
            u=x[o+1]; v=make_float2(-x[o+3].y, x[o+3].x);
            x[o+1]=cadd(u,v); x[o+3]=csub(u,v);
        }
        // inv H=4: conjW = e^{+i*pi*r/4}
        { float2 u=x[0], v=x[4]; x[0]=cadd(u,v); x[4]=csub(u,v); }
        { float2 u=x[1], v=cmul(x[5], make_float2(C8v,C8v));
          x[1]=cadd(u,v); x[5]=csub(u,v); }
        { float2 u=x[2], v=make_float2(-x[6].y, x[6].x);
          x[2]=cadd(u,v); x[6]=csub(u,v); }
        { float2 u=x[3], v=cmul(x[7], make_float2(-C8v,C8v));
          x[3]=cadd(u,v); x[7]=csub(u,v); }
        #pragma unroll
        for (int r = 0; r < 8; ++r) y[PIDX(p + r)] = x[r];
    }
    __syncthreads();

    inv4<3>(y, tw, 2 * q); inv4<3>(y, tw, 2 * q + 1); // stages 3,4
    __syncthreads();
    inv8<5>(y, tw, q);                                // stages 5,6,7
    __syncthreads();

    // ---- iP1: inv stages 8,9,10; in-place on the SAME padded slots
    // (read PIDX, write PIDX -> per-thread disjoint, no cross-warp race).
    {
        #pragma unroll
        for (int r = 0; r < 8; ++r) x[r] = y[PIDX(q + 256 * r)];
        float2 wc0 = tw[q << 2];
        float2 wc  = make_float2(wc0.x, -wc0.y);
        #pragma unroll
        for (int g = 0; g < 4; ++g) {
            float2 v = cmul(x[2*g+1], wc);
            float2 u = x[2*g];
            x[2*g] = cadd(u, v); x[2*g+1] = csub(u, v);
        }
        float2 wb0  = tw[q << 1];
        float2 wb0c = make_float2(wb0.x, -wb0.y);
        float2 wb1c = make_float2(wb0.y, wb0.x);
        #pragma unroll
        for (int o = 0; o < 8; o += 4) {
            float2 v = cmul(x[o+2], wb0c);
            float2 u = x[o];
            x[o] = cadd(u, v); x[o+2] = csub(u, v);
            v = cmul(x[o+3], wb1c);
            u = x[o+1];
            x[o+1] = cadd(u, v); x[o+3] = csub(u, v);
        }
        #pragma unroll
        for (int r = 0; r < 4; ++r) {
            float2 wa0 = tw[q + 256 * r];
            float2 wac = make_float2(wa0.x, -wa0.y);
            float2 v = cmul(x[r+4], wac);
            float2 u = x[r];
            x[r] = cadd(u, v); x[r+4] = csub(u, v);
        }
        #pragma unroll
        for (int r = 0; r < 8; ++r) y[PIDX(q + 256 * r)] = x[r];
    }
    __syncthreads();

    // ---- Epilogue: all 512 threads; pilots re-read from global (L1-warm);
    // odd values read from padded slots PIDX(m) (natural order).
    if (MODE == 0) {
        float e2[4], e11[4], d2[4], d11[4];
        #pragma unroll
        for (int s = 0; s < 4; ++s) {
            int m = tid + 512 * s;
            e2[s]  = rb[m];
            e11[s] = rb[MM + m];
            d2[s]  = y2s[PIDX(m)].x;
            d11[s] = y11s[PIDX(m)].x;
        }
        #pragma unroll
        for (int t = 0; t < NSYM; ++t) {
            float a = (t <= 2) ? 0.0f : (t >= 11 ? 1.0f : (float)(t - 2) * (1.0f / 9.0f));
            size_t base = ((size_t)b * NSYM + t) * MM;
            #pragma unroll
            for (int s = 0; s < 4; ++s) {
                int m = tid + 512 * s;
                float2 v;
                v.x = fmaf(a, e11[s] - e2[s], e2[s]);
                v.y = fmaf(a, d11[s] - d2[s], d2[s]);
                ((float2*)outv)[base + m] = v;
            }
        }
    } else {
        #pragma unroll
        for (int s = 0; s < 4; ++s) {
            int m = tid + 512 * s;
            float2 e2  = make_float2(rb[m], ib[m]);
            float2 e11 = make_float2(rb[MM + m], ib[MM + m]);
            float2 d2  = y2s[PIDX(m)];
            float2 d11 = y11s[PIDX(m)];
            #pragma unroll
            for (int t = 0; t < NSYM; ++t) {
                float a = (t <= 2) ? 0.0f : (t >= 11 ? 1.0f : (float)(t - 2) * (1.0f / 9.0f));
                size_t base = ((size_t)b * NSYM + t) * MM;
                float4 v;
                v.x = fmaf(a, e11.x - e2.x, e2.x);
                v.y = fmaf(a, e11.y - e2.y, e2.y);
                v.z = fmaf(a, d11.x - d2.x, d2.x);
                v.w = fmaf(a, d11.y - d2.y, d2.y);
                ((float4*)outv)[base + m] = v;
            }
        }
    }
}

extern "C" void kernel_launch(void* const* d_in, const int* in_sizes, int n_in,
                              void* d_out, int out_size)
{
    const float* re = (const float*)d_in[0];
    const float* im = (const float*)d_in[1];
    const int B = in_sizes[0] / 4096;
    const long long interleaved = (long long)B * NSYM * 4096 * 2;

    if ((long long)out_size >= interleaved)
        tdi_kernel<1><<<B, THREADS>>>(re, im, d_out);
    else
        tdi_kernel<0><<<B, THREADS>>>(re, im, d_out);
}